// round 1
// baseline (speedup 1.0000x reference)
#include <cuda_runtime.h>

// Problem constants (fixed by setup_inputs): B=8, N=20, K=5, Q=15, D=1024
#define BB    8
#define NN    20
#define KSUP  5
#define QQ    15
#define DD    1024
#define ROWS  (KSUP + QQ)        // 20 rows per (b,n)
#define NQ    (NN * QQ)          // 300 queries per batch
#define D4    (DD / 4)           // 256 float4 per row
#define TASKS (BB * NQ / 2)      // 1200 query-pair tasks

// Scratch (device globals — no allocation allowed)
__device__ float g_proto[BB * NN * DD];   // 640 KB, L2-resident
__device__ float g_termp[BB * NN];

// ---------------------------------------------------------------------------
// K1: proto[b,n,:] = mean_j support, term_p[b,n] = proto . w0
// grid = 160 blocks (one per (b,n)), 256 threads (one float4 per thread)
// ---------------------------------------------------------------------------
__global__ __launch_bounds__(256) void proto_kernel(
    const float* __restrict__ emb, const float* __restrict__ weight)
{
    int bn = blockIdx.x;             // b*20 + n
    int t  = threadIdx.x;            // float4 index 0..255
    const float4* base = reinterpret_cast<const float4*>(emb) + (size_t)bn * ROWS * D4;

    float4 s = base[t];
#pragma unroll
    for (int j = 1; j < KSUP; j++) {
        float4 v = base[j * D4 + t];
        s.x += v.x; s.y += v.y; s.z += v.z; s.w += v.w;
    }
    s.x *= 0.2f; s.y *= 0.2f; s.z *= 0.2f; s.w *= 0.2f;
    reinterpret_cast<float4*>(g_proto)[(size_t)bn * D4 + t] = s;

    float4 w0 = reinterpret_cast<const float4*>(weight)[t];
    float tp = s.x * w0.x + s.y * w0.y + s.z * w0.z + s.w * w0.w;
#pragma unroll
    for (int off = 16; off; off >>= 1) tp += __shfl_xor_sync(0xFFFFFFFFu, tp, off);

    __shared__ float red[8];
    if ((t & 31) == 0) red[t >> 5] = tp;
    __syncthreads();
    if (t == 0) {
        float r = 0.f;
#pragma unroll
        for (int w = 0; w < 8; w++) r += red[w];
        g_termp[bn] = r;
    }
}

// ---------------------------------------------------------------------------
// Main: persistent, one block per SM. 10 warps/block; each warp owns a pair of
// query rows in registers (q, q*w3, plus shared w2). Proto for current batch
// lives in 80KB smem; inner loop is 1x LDS.128 + 24 FMA-pipe ops per 4 d
// serving BOTH queries -> FMA-bound.
// ---------------------------------------------------------------------------
__global__ __launch_bounds__(320, 1) void relnet_kernel(
    const float* __restrict__ emb,
    const float* __restrict__ weight,
    const float* __restrict__ bias,
    float* __restrict__ out)
{
    extern __shared__ float smem[];
    float4* sP4  = reinterpret_cast<float4*>(smem);   // NN*D4 float4 = 80KB
    float*  sTp  = smem + NN * DD;                    // 20 floats

    const int tid  = threadIdx.x;
    const int lane = tid & 31;
    const int warp = tid >> 5;
    const int G    = gridDim.x;

    const int tLo = (int)(((long long)blockIdx.x       * TASKS) / G);
    const int tHi = (int)(((long long)(blockIdx.x + 1) * TASKS) / G);
    const int myT = tLo + warp;
    const bool active = (myT < tHi);
    const int bLo = (2 * tLo) / NQ;
    const int bHi = (tHi > tLo) ? (2 * (tHi - 1)) / NQ : bLo;

    const float4* emb4 = reinterpret_cast<const float4*>(emb);
    const float4* w14  = reinterpret_cast<const float4*>(weight) + 1 * 256;
    const float4* w24  = reinterpret_cast<const float4*>(weight) + 2 * 256;
    const float4* w34  = reinterpret_cast<const float4*>(weight) + 3 * 256;
    const float4* gP4  = reinterpret_cast<const float4*>(g_proto);
    const float bi = bias[0];

    for (int b = bLo; b <= bHi; b++) {
        __syncthreads();   // protect smem from previous iteration's readers
        for (int idx = tid; idx < NN * D4; idx += 320)
            sP4[idx] = gP4[(size_t)b * NN * D4 + idx];
        if (tid < NN) sTp[tid] = g_termp[b * NN + tid];
        __syncthreads();

        if (!active || (2 * myT) / NQ != b) continue;

        const int q0 = 2 * myT - b * NQ;      // 0..298 (even)
        const int q1 = q0 + 1;
        const float4* r0 = emb4 + ((size_t)((b * NN + q0 / QQ) * ROWS + KSUP + q0 % QQ)) * D4;
        const float4* r1 = emb4 + ((size_t)((b * NN + q1 / QQ) * ROWS + KSUP + q1 % QQ)) * D4;

        float4 q0v[8], q1v[8], c0v[8], c1v[8], w2v[8];
        float tq0 = 0.f, tq1 = 0.f;
#pragma unroll
        for (int i = 0; i < 8; i++) {
            const int idx = i * 32 + lane;
            float4 a  = r0[idx];
            float4 c  = r1[idx];
            float4 w3 = w34[idx];
            float4 w1 = w14[idx];
            w2v[i] = w24[idx];
            q0v[i] = a; q1v[i] = c;
            c0v[i] = make_float4(a.x * w3.x, a.y * w3.y, a.z * w3.z, a.w * w3.w);
            c1v[i] = make_float4(c.x * w3.x, c.y * w3.y, c.z * w3.z, c.w * w3.w);
            tq0 += a.x * w1.x + a.y * w1.y + a.z * w1.z + a.w * w1.w;
            tq1 += c.x * w1.x + c.y * w1.y + c.z * w1.z + c.w * w1.w;
        }
#pragma unroll
        for (int off = 16; off; off >>= 1) {
            tq0 += __shfl_xor_sync(0xFFFFFFFFu, tq0, off);
            tq1 += __shfl_xor_sync(0xFFFFFFFFu, tq1, off);
        }

        float* o0 = out + ((size_t)b * NQ + q0) * NN;
        float* o1 = o0 + NN;

#pragma unroll 1
        for (int n = 0; n < NN; n++) {
            const float4* pr = sP4 + n * D4;
            float aA0 = 0.f, aC0 = 0.f, aA1 = 0.f, aC1 = 0.f;
#pragma unroll
            for (int i = 0; i < 8; i++) {
                const float4 p = pr[i * 32 + lane];
                aA0 = fmaf(fabsf(p.x - q0v[i].x), w2v[i].x, aA0);
                aA0 = fmaf(fabsf(p.y - q0v[i].y), w2v[i].y, aA0);
                aA0 = fmaf(fabsf(p.z - q0v[i].z), w2v[i].z, aA0);
                aA0 = fmaf(fabsf(p.w - q0v[i].w), w2v[i].w, aA0);
                aC0 = fmaf(p.x, c0v[i].x, aC0);
                aC0 = fmaf(p.y, c0v[i].y, aC0);
                aC0 = fmaf(p.z, c0v[i].z, aC0);
                aC0 = fmaf(p.w, c0v[i].w, aC0);
                aA1 = fmaf(fabsf(p.x - q1v[i].x), w2v[i].x, aA1);
                aA1 = fmaf(fabsf(p.y - q1v[i].y), w2v[i].y, aA1);
                aA1 = fmaf(fabsf(p.z - q1v[i].z), w2v[i].z, aA1);
                aA1 = fmaf(fabsf(p.w - q1v[i].w), w2v[i].w, aA1);
                aC1 = fmaf(p.x, c1v[i].x, aC1);
                aC1 = fmaf(p.y, c1v[i].y, aC1);
                aC1 = fmaf(p.z, c1v[i].z, aC1);
                aC1 = fmaf(p.w, c1v[i].w, aC1);
            }
            float s0 = aA0 + aC0;
            float s1 = aA1 + aC1;
#pragma unroll
            for (int off = 16; off; off >>= 1) {
                s0 += __shfl_xor_sync(0xFFFFFFFFu, s0, off);
                s1 += __shfl_xor_sync(0xFFFFFFFFu, s1, off);
            }
            if (lane == 0) {
                const float tp = sTp[n];
                o0[n] = s0 + tp + tq0 + bi;
                o1[n] = s1 + tp + tq1 + bi;
            }
        }
    }
}

// ---------------------------------------------------------------------------
// Launch
// ---------------------------------------------------------------------------
static const int SMEM_BYTES = (NN * DD + 32) * (int)sizeof(float);  // 82,176 B

extern "C" void kernel_launch(void* const* d_in, const int* in_sizes, int n_in,
                              void* d_out, int out_size)
{
    const float* emb    = (const float*)d_in[0];
    const float* weight = (const float*)d_in[1];
    const float* bias   = (const float*)d_in[2];
    float* out          = (float*)d_out;

    cudaFuncSetAttribute(relnet_kernel,
                         cudaFuncAttributeMaxDynamicSharedMemorySize, SMEM_BYTES);

    int dev = 0;
    cudaGetDevice(&dev);
    int sms = 148;
    cudaDeviceGetAttribute(&sms, cudaDevAttrMultiProcessorCount, dev);
    if (sms < 1) sms = 148;
    if (sms > TASKS) sms = TASKS;

    proto_kernel<<<BB * NN, 256>>>(emb, weight);
    relnet_kernel<<<sms, 320, SMEM_BYTES>>>(emb, weight, bias, out);
}